// round 12
// baseline (speedup 1.0000x reference)
#include <cuda_runtime.h>
#include <cuda_bf16.h>
#include <cuda_fp16.h>
#include <cstdint>

// ---------------------------------------------------------------------------
// out[n] = ||delta_n||^2 (exact fp32) + (1/512)*delta @ W @ delta^T
// W = 512*(S_inv-I), symmetric => lower-triangle 128x128 blocks only,
// off-diagonal weight 2 pre-folded into W.  fp8 e4m3 mma.sync m16n8k32.
// Persistent CTA (grid 148, 512 thr): phase-1 of block j+148 is interleaved
// row-by-row into the 10-tile GEMM loop of block j (all 16 warps do both).
// ---------------------------------------------------------------------------

#define NROWS   65536
#define NBLK    512
#define GRID    148
#define THREADS 512

// fp8 weighted 512*(S_inv - I), 16 tiles of 16KB: tile t=(n>>7)*4+(k>>7),
// in-tile: nn*128 + (kk ^ ((nn&7)<<4))  -- SMEM image == GMEM image.
__device__ __align__(16) unsigned char g_B[512 * 512];

__constant__ int c_nc[10] = {0,1,1,2,2,2,3,3,3,3};
__constant__ int c_kc[10] = {0,0,1,0,1,2,0,1,2,3};

#define SM_ROWSQ 0                       // 2 x 128 floats
#define SM_PART  1024                    // 512 floats
#define SM_A     4096                    // 2 x 65536 fp8 delta (swizzled)
#define SM_B     (SM_A + 2 * 65536)      // 3 x 16384
#define SM_TOTAL (SM_B + 3 * 16384)      // 184320 bytes

__device__ __forceinline__ uint32_t smem_u32(const void* p) {
    uint32_t a;
    asm("{ .reg .u64 t; cvta.to.shared.u64 t, %1; cvt.u32.u64 %0, t; }"
        : "=r"(a) : "l"(p));
    return a;
}

__device__ __forceinline__ void ldsm4(uint32_t* r, uint32_t addr) {
    asm volatile("ldmatrix.sync.aligned.m8n8.x4.shared.b16 {%0,%1,%2,%3}, [%4];"
                 : "=r"(r[0]), "=r"(r[1]), "=r"(r[2]), "=r"(r[3]) : "r"(addr));
}

__device__ __forceinline__ void mma16832(float* d, const uint32_t* a,
                                         const uint32_t* b) {
    asm volatile(
        "mma.sync.aligned.m16n8k32.row.col.f32.e4m3.e4m3.f32 "
        "{%0,%1,%2,%3}, {%4,%5,%6,%7}, {%8,%9}, {%0,%1,%2,%3};"
        : "+f"(d[0]), "+f"(d[1]), "+f"(d[2]), "+f"(d[3])
        : "r"(a[0]), "r"(a[1]), "r"(a[2]), "r"(a[3]),
          "r"(b[0]), "r"(b[1]));
}

__device__ __forceinline__ void cp16(uint32_t dst, const void* src) {
    asm volatile("cp.async.cg.shared.global [%0], [%1], 16;"
                 :: "r"(dst), "l"(src));
}

__device__ __forceinline__ uint16_t f2e4m3x2(float hi, float lo) {
    uint16_t r;
    asm("cvt.rn.satfinite.e4m3x2.f32 %0, %1, %2;" : "=h"(r) : "f"(hi), "f"(lo));
    return r;
}

__device__ __forceinline__ float2 e4m3x2_2f(uint16_t v) {
    uint32_t h;
    asm("cvt.rn.f16x2.e4m3x2 %0, %1;" : "=r"(h) : "h"(v));
    return __half22float2(*reinterpret_cast<__half2*>(&h));
}

// ---------------------------------------------------------------------------
__global__ void __launch_bounds__(256, 4)
prep_kernel(const float* __restrict__ S) {
    int p = blockIdx.x * 256 + threadIdx.x;
    int n = p >> 8;
    int k = (p & 255) << 1;
    float wgt = ((n >> 7) == (k >> 7)) ? 512.0f : 1024.0f;
    float v0 = (S[n * 512 + k]     - (n == k     ? 1.0f : 0.0f)) * wgt;
    float v1 = (S[n * 512 + k + 1] - (n == k + 1 ? 1.0f : 0.0f)) * wgt;
    int t = (n >> 7) * 4 + (k >> 7);
    uint32_t nn = (uint32_t)(n & 127), kk = (uint32_t)(k & 127);
    uint32_t off = (uint32_t)(t * 16384) + nn * 128 + (kk ^ ((nn & 7) << 4));
    *(uint16_t*)(g_B + off) = f2e4m3x2(v1, v0);
}

// ---------------------------------------------------------------------------
extern __shared__ unsigned char smem[];

// one phase-1 row: delta, exact fp32 rowsq, fp8 delta into swizzled A buffer
__device__ __forceinline__ void phase1_row(
    const float4* __restrict__ x4, const float4* __restrict__ f4,
    int m0, int r, unsigned char* abuf, float* rowsqb, int lane) {
    long gbase = (long)(m0 + r) * 128;
    float sq = 0.0f;
    uint32_t rswz = (uint32_t)(r & 7) << 4;
    #pragma unroll
    for (int q = 0; q < 4; q++) {
        int c4 = lane + q * 32;
        float4 xv = x4[gbase + c4];
        float4 fv = f4[gbase + c4];
        float d0 = xv.x - fv.x, d1 = xv.y - fv.y;
        float d2 = xv.z - fv.z, d3 = xv.w - fv.w;
        sq += d0 * d0 + d1 * d1 + d2 * d2 + d3 * d3;
        uint32_t v = (uint32_t)f2e4m3x2(d1, d0)
                   | ((uint32_t)f2e4m3x2(d3, d2) << 16);
        uint32_t off = (uint32_t)(r * 512) + (((uint32_t)(c4 * 4)) ^ rswz);
        *(uint32_t*)(abuf + off) = v;
    }
    #pragma unroll
    for (int o = 16; o; o >>= 1)
        sq += __shfl_xor_sync(0xffffffffu, sq, o);
    if (lane == 0) rowsqb[r] = sq;
}

__global__ void __launch_bounds__(THREADS, 1)
mahal_kernel(const float4* __restrict__ x4, const float4* __restrict__ f4,
             float* __restrict__ out) {
    const int tid  = threadIdx.x;
    const int wid  = tid >> 5;
    const int lane = tid & 31;
    const int bid  = blockIdx.x;
    const uint32_t sbase = smem_u32(smem);
    float* part = (float*)(smem + SM_PART);

    const int nmy  = (NBLK - 1 - bid) / GRID + 1;
    const int ftot = nmy * 10;

    // --- prefetch B flat-tiles f=0 (tile 0) and f=1 (tile 4) ---
    #pragma unroll
    for (int t = 0; t < 2; t++) {
        uint32_t dst = sbase + SM_B + t * 16384;
        const unsigned char* src = g_B + (t ? 4 : 0) * 16384;
        #pragma unroll
        for (int i = 0; i < 2; i++) {
            int e = tid + i * THREADS;
            cp16(dst + e * 16, src + e * 16);
        }
        asm volatile("cp.async.commit_group;");
    }

    // --- prologue: phase 1 of first block into A[0] ---
    {
        const int m0 = bid * 128;
        #pragma unroll
        for (int rr = 0; rr < 8; rr++)
            phase1_row(x4, f4, m0, wid * 8 + rr,
                       smem + SM_A, (float*)(smem + SM_ROWSQ), lane);
    }
    __syncthreads();

    // --- warp tiling: 16 warps, warp tile 32M x 32N ---
    const int mb = wid >> 2;
    const int nb = wid & 3;
    const uint32_t aswz  = (uint32_t)(lane & 7) << 4;
    const uint32_t akoff = (uint32_t)(lane >> 4) << 4;
    const int bn1 = (lane & 7) + ((lane >> 4) << 3);
    const uint32_t bkoff = (uint32_t)((lane >> 3) & 1) << 4;

    uint32_t a_row[2];
    #pragma unroll
    for (int sm = 0; sm < 2; sm++)
        a_row[sm] = (uint32_t)((mb * 32 + sm * 16 + (lane & 15)) * 512);
    uint32_t b_off[2];
    #pragma unroll
    for (int sn = 0; sn < 2; sn++)
        b_off[sn] = (uint32_t)((nb * 32 + sn * 16 + bn1) * 128);

    const int rq = lane >> 2;
    const uint32_t d_swz = (uint32_t)rq << 4;
    uint32_t d_base[2];
    #pragma unroll
    for (int sm = 0; sm < 2; sm++)
        d_base[sm] = (uint32_t)((mb * 32 + sm * 16 + rq) * 512);

    int f = 0, jj = 0;
    for (int blk = bid; blk < NBLK; blk += GRID, jj++) {
        const int b = jj & 1;
        const uint32_t aoff = (uint32_t)(SM_A + b * 65536);
        unsigned char* anext = smem + SM_A + (b ^ 1) * 65536;
        float* rowsqn = (float*)(smem + SM_ROWSQ + (b ^ 1) * 512);
        const bool hn = (blk + GRID) < NBLK;
        const int m0 = blk * 128;

        float acc[2][4][4];
        float zl[2] = {0, 0}, zh[2] = {0, 0};

        #pragma unroll 1
        for (int ti = 0; ti < 10; ti++, f++) {
            asm volatile("cp.async.wait_group 1;" ::: "memory");
            __syncthreads();

            // issue prefetch for flat-tile f+2 into buffer (f+2)%3
            if (f + 2 < ftot) {
                int ii = (f + 2) % 10;
                int tile = c_nc[ii] * 4 + c_kc[ii];
                uint32_t dst = sbase + SM_B + ((f + 2) % 3) * 16384;
                const unsigned char* src = g_B + tile * 16384;
                #pragma unroll
                for (int i = 0; i < 2; i++) {
                    int e = tid + i * THREADS;
                    cp16(dst + e * 16, src + e * 16);
                }
            }
            asm volatile("cp.async.commit_group;");

            const int nc = c_nc[ti], kc = c_kc[ti];
            const uint32_t btile = sbase + SM_B + (f % 3) * 16384;

            if (ti == 0 || ti == 1 || ti == 3 || ti == 6) {
                #pragma unroll
                for (int sm = 0; sm < 2; sm++)
                    #pragma unroll
                    for (int j = 0; j < 4; j++)
                        #pragma unroll
                        for (int q = 0; q < 4; q++)
                            acc[sm][j][q] = 0.0f;
            }

            #pragma unroll
            for (int s = 0; s < 4; s++) {
                uint32_t af[2][4], bf[2][4];
                uint32_t akb = (uint32_t)(kc * 128 + s * 32);
                #pragma unroll
                for (int sm = 0; sm < 2; sm++)
                    ldsm4(af[sm], sbase + aoff + a_row[sm]
                          + ((akb + akoff) ^ aswz));
                #pragma unroll
                for (int sn = 0; sn < 2; sn++)
                    ldsm4(bf[sn], btile + b_off[sn]
                          + (((uint32_t)(s * 32) + bkoff) ^ aswz));
                #pragma unroll
                for (int sm = 0; sm < 2; sm++)
                    #pragma unroll
                    for (int j = 0; j < 4; j++)
                        mma16832(acc[sm][j], af[sm], bf[j >> 1] + (j & 1) * 2);
            }

            if (ti == 0 || ti == 2 || ti == 5 || ti == 9) {
                // fused dot for completed nc-group (weights folded into B)
                #pragma unroll
                for (int sm = 0; sm < 2; sm++) {
                    #pragma unroll
                    for (int j = 0; j < 4; j++) {
                        uint32_t kbyte = (uint32_t)(nc * 128 + nb * 32 + j * 8
                                                    + (lane & 3) * 2);
                        uint32_t off = kbyte ^ d_swz;
                        uint16_t vlo = *(const uint16_t*)(smem + aoff
                                           + d_base[sm] + off);
                        uint16_t vhi = *(const uint16_t*)(smem + aoff
                                           + d_base[sm] + 8 * 512 + off);
                        float2 flo = e4m3x2_2f(vlo);
                        float2 fhi = e4m3x2_2f(vhi);
                        zl[sm] += flo.x * acc[sm][j][0] + flo.y * acc[sm][j][1];
                        zh[sm] += fhi.x * acc[sm][j][2] + fhi.y * acc[sm][j][3];
                    }
                }
            }

            // interleaved phase-1 row of NEXT block (tiles 0..7)
            if (hn && ti < 8)
                phase1_row(x4, f4, m0 + GRID * 128, wid * 8 + ti,
                           anext, rowsqn, lane);
        }

        // --- block epilogue ---
        #pragma unroll
        for (int sm = 0; sm < 2; sm++) {
            zl[sm] += __shfl_xor_sync(0xffffffffu, zl[sm], 1);
            zl[sm] += __shfl_xor_sync(0xffffffffu, zl[sm], 2);
            zh[sm] += __shfl_xor_sync(0xffffffffu, zh[sm], 1);
            zh[sm] += __shfl_xor_sync(0xffffffffu, zh[sm], 2);
        }
        if ((lane & 3) == 0) {
            #pragma unroll
            for (int sm = 0; sm < 2; sm++) {
                int row = mb * 32 + sm * 16 + rq;
                part[nb * 128 + row]     = zl[sm];
                part[nb * 128 + row + 8] = zh[sm];
            }
        }
        __syncthreads();
        if (tid < 128) {
            const float* rowsqb = (const float*)(smem + SM_ROWSQ + b * 512);
            out[m0 + tid] = rowsqb[tid]
                          + (part[tid] + part[128 + tid]
                             + part[256 + tid] + part[384 + tid])
                            * (1.0f / 512.0f);
        }
    }
}

// ---------------------------------------------------------------------------
extern "C" void kernel_launch(void* const* d_in, const int* in_sizes, int n_in,
                              void* d_out, int out_size) {
    const float* x  = (const float*)d_in[0];
    const float* xf = (const float*)d_in[1];
    const float* S  = (const float*)d_in[2];
    float* out = (float*)d_out;

    cudaFuncSetAttribute(mahal_kernel,
                         cudaFuncAttributeMaxDynamicSharedMemorySize, SM_TOTAL);

    prep_kernel<<<512, 256>>>(S);
    mahal_kernel<<<GRID, THREADS, SM_TOTAL>>>(
        (const float4*)x, (const float4*)xf, out);
}